// round 11
// baseline (speedup 1.0000x reference)
#include <cuda_runtime.h>
#include <stdint.h>
#include <cub/block/block_radix_sort.cuh>

// Shapes (fixed): seq (16,4096,1024) f32, attn_weights (16,4096) f32,
// out (16,2049,1024) f32.
#define BB 16
#define NN 4096
#define DD 1024
#define KK 2048
#define D4 (DD / 4)
#define CHUNK 1024                    // elements per chunk-sort CTA
#define NRUNS (NN / CHUNK)            // 4 sorted runs per batch
#define GROUP 16                      // rows per copy CTA
#define SELGROUPS (KK / GROUP)        // 128 copy CTAs per batch
#define PR_GROUP 64                   // rows per pruned-sum CTA
#define PRCH (KK / PR_GROUP)          // 32 pruned partials per batch

typedef unsigned long long u64;

__device__ u64   g_run[BB * NN];               // chunk-sorted composite keys
__device__ int   g_sorted[BB * NN];
__device__ float g_partial[BB * PRCH * DD];    // 2 MB scratch
__device__ int   g_count_sort[BB];             // sort-phase tickets (self-resetting)
__device__ int   g_count_mix[BB];              // mix-phase tickets (self-resetting)

// ---------------------------------------------------------------------------
// Fused sort+rank. Grid (4, BB) = 64 CTAs, 256 threads x 4 items.
// Each CTA radix-sorts its 1024-chunk (key = ~mono(f32): ascending u32 ==
// descending weight; CUB stable => ascending index on ties; packed
// u64 = (key<<32)|idx is unique and orders exactly like jax.lax.top_k).
// The last-arriving CTA per batch (release-fence + ticket + acquire-fence)
// stages all 4 runs in smem and computes every element's exact global rank
// (local pos + 3x lower_bound via fixed-step searches + correction probe),
// scattering token indices to g_sorted.
// ---------------------------------------------------------------------------
__global__ __launch_bounds__(256) void sort_rank_kernel(const float* __restrict__ w) {
    typedef cub::BlockRadixSort<unsigned int, 256, 4, int, 5> Sorter;
    __shared__ typename Sorter::TempStorage temp;
    __shared__ u64 runs[NN];    // 32 KB (used only by the last CTA per batch)
    __shared__ int ticket;

    const int b = blockIdx.y;
    const int c = blockIdx.x;
    const int t = threadIdx.x;

    unsigned int keys[4];
    int vals[4];
#pragma unroll
    for (int p = 0; p < 4; p++) {
        int i = c * CHUNK + 4 * t + p;
        unsigned int u = __float_as_uint(w[b * NN + i]);
        unsigned int mono = (u & 0x80000000u) ? ~u : (u | 0x80000000u);
        keys[p] = ~mono;
        vals[p] = i;
    }

    Sorter(temp).Sort(keys, vals);   // stable, blocked arrangement

#pragma unroll
    for (int p = 0; p < 4; p++)
        g_run[b * NN + c * CHUNK + 4 * t + p] =
            ((u64)keys[p] << 32) | (unsigned int)vals[p];

    // release: run writes visible before ticket increment
    __threadfence();
    __syncthreads();
    if (t == 0) ticket = atomicAdd(&g_count_sort[b], 1);
    __syncthreads();
    if (ticket != NRUNS - 1) return;

    // acquire: order peer-run reads after observing the last ticket
    __threadfence();

    const u64* base = g_run + b * NN;
#pragma unroll
    for (int s = 0; s < NN / 256; s++)
        runs[t + s * 256] = __ldcg(base + t + s * 256);
    __syncthreads();

#pragma unroll
    for (int s = 0; s < NN / 256; s++) {
        const int i = t + s * 256;                   // element slot 0..4095
        const int r = i >> 10;                       // owning run
        const int p = i & (CHUNK - 1);               // pos within run
        const u64 key = runs[i];

        const u64* A0 = runs + (((r + 1) & 3) << 10);
        const u64* A1 = runs + (((r + 2) & 3) << 10);
        const u64* A2 = runs + (((r + 3) & 3) << 10);

        int c0 = 0, c1 = 0, c2 = 0;
#pragma unroll
        for (int step = CHUNK / 2; step > 0; step >>= 1) {
            if (A0[c0 + step - 1] < key) c0 += step;
            if (A1[c1 + step - 1] < key) c1 += step;
            if (A2[c2 + step - 1] < key) c2 += step;
        }
        // fixed steps sum to 1023; count may be 1024 (all smaller)
        if (A0[c0] < key) c0++;
        if (A1[c1] < key) c1++;
        if (A2[c2] < key) c2++;

        g_sorted[b * NN + p + c0 + c1 + c2] = (int)(key & 0xFFFFFFFFu);
    }

    if (t == 0) g_count_sort[b] = 0;    // reset for next graph replay
}

// ---------------------------------------------------------------------------
// Fused gather/sum/mix, asymmetric grid: per batch, blocks [0,PRCH) each sum
// 64 pruned rows into one partial (launched first -- they run longest); the
// last-arriving sum CTA per batch (release+ticket+acquire) reduces the 32
// L2-resident partials into the mix row. Blocks [PRCH, PRCH+SELGROUPS) copy
// 16 selected rows each. Every seq byte read exactly once; streaming
// loads/stores (data >> L2). __launch_bounds__(256,4) keeps 4 CTAs/SM
// resident for more outstanding sectors against HBM.
// ---------------------------------------------------------------------------
__global__ __launch_bounds__(256, 4) void gather_sum_kernel(const float4* __restrict__ seq,
                                                            float4* __restrict__ out) {
    const int b = blockIdx.y;
    const int g = blockIdx.x;
    const int tid = threadIdx.x;

    const float4* sb = seq + (size_t)b * NN * D4;

    if (g < PRCH) {
        // pruned-sum CTA: tokens at sorted positions [KK + g*64, KK + (g+1)*64)
        __shared__ int toks[PR_GROUP];
        __shared__ int ticket;
        if (tid < PR_GROUP) toks[tid] = g_sorted[b * NN + KK + g * PR_GROUP + tid];
        __syncthreads();

        float4 acc = make_float4(0.f, 0.f, 0.f, 0.f);
#pragma unroll 8
        for (int t = 0; t < PR_GROUP; t++) {
            float4 v = __ldcs(sb + (size_t)toks[t] * D4 + tid);
            acc.x += v.x; acc.y += v.y; acc.z += v.z; acc.w += v.w;
        }
        float4* part = reinterpret_cast<float4*>(g_partial);
        part[((size_t)b * PRCH + g) * D4 + tid] = acc;

        // release: partial visible before ticket
        __threadfence();
        if (tid == 0) ticket = atomicAdd(&g_count_mix[b], 1);
        __syncthreads();
        if (ticket == PRCH - 1) {
            // acquire: order partial reads after observing the last ticket
            __threadfence();
            const float4* pbase = part + (size_t)b * PRCH * D4 + tid;
            float4 s = make_float4(0.f, 0.f, 0.f, 0.f);
#pragma unroll
            for (int c = 0; c < PRCH; c++) {
                float4 v = __ldcg(pbase + (size_t)c * D4);
                s.x += v.x; s.y += v.y; s.z += v.z; s.w += v.w;
            }
            const float scale = 0.05f / (2048.0f + 1e-10f);
            s.x *= scale; s.y *= scale; s.z *= scale; s.w *= scale;
            out[((size_t)b * (KK + 1) + KK) * D4 + tid] = s;
            if (tid == 0) g_count_mix[b] = 0;   // reset for next graph replay
        }
    } else {
        // copy CTA: sorted positions [j0, j0+16), in 4 batches of 4 rows
        const int j0 = (g - PRCH) * GROUP;
        __shared__ int toks[GROUP];
        if (tid < GROUP) toks[tid] = g_sorted[b * NN + j0 + tid];
        __syncthreads();

        float4* dst = out + ((size_t)b * (KK + 1) + j0) * D4 + tid;
#pragma unroll
        for (int h = 0; h < 4; h++) {
            float4 v[4];
#pragma unroll
            for (int t = 0; t < 4; t++)
                v[t] = __ldcs(sb + (size_t)toks[h * 4 + t] * D4 + tid);
#pragma unroll
            for (int t = 0; t < 4; t++)
                __stcs(dst + (size_t)(h * 4 + t) * D4, v[t]);
        }
    }
}

// ---------------------------------------------------------------------------
extern "C" void kernel_launch(void* const* d_in, const int* in_sizes, int n_in,
                              void* d_out, int out_size) {
    const float* seq = (const float*)d_in[0];
    const float* attn_weights = (const float*)d_in[1];
    float* out = (float*)d_out;
    (void)in_sizes; (void)n_in; (void)out_size;

    dim3 sgrid(NRUNS, BB);                // (4, 16)
    sort_rank_kernel<<<sgrid, 256>>>(attn_weights);

    dim3 fgrid(PRCH + SELGROUPS, BB);     // (160, 16)
    gather_sum_kernel<<<fgrid, 256>>>((const float4*)seq, (float4*)out);
}

// round 12
// speedup vs baseline: 1.0875x; 1.0875x over previous
#include <cuda_runtime.h>
#include <stdint.h>
#include <cub/block/block_radix_sort.cuh>

// Shapes (fixed): seq (16,4096,1024) f32, attn_weights (16,4096) f32,
// out (16,2049,1024) f32.
#define BB 16
#define NN 4096
#define DD 1024
#define KK 2048
#define D4 (DD / 4)
#define CHUNK 1024                    // elements per chunk-sort CTA
#define NRUNS (NN / CHUNK)            // 4 sorted runs per batch
#define GROUP 16                      // rows per copy CTA
#define SELGROUPS (KK / GROUP)        // 128 copy CTAs per batch
#define PR_GROUP 64                   // rows per pruned-sum CTA
#define PRCH (KK / PR_GROUP)          // 32 pruned partials per batch

typedef unsigned long long u64;

__device__ u64   g_run[BB * NN];               // chunk-sorted composite keys
__device__ int   g_sorted[BB * NN];
__device__ float g_partial[BB * PRCH * DD];    // 2 MB scratch
__device__ int   g_count_mix[BB];              // mix tickets (self-resetting)

// ---------------------------------------------------------------------------
// S1: sort 4 chunks of 1024 per batch. Grid (4, BB) = 64 CTAs, 256x4.
// Key = ~mono(f32) (ascending u32 == descending weight); CUB stable sort
// preserves ascending index on ties. Packed u64 = (key<<32)|idx gives the
// rank kernel a unique comparison value; composite order == jax.lax.top_k
// order (desc value, asc index on ties).
// ---------------------------------------------------------------------------
__global__ __launch_bounds__(256) void sort_chunks_kernel(const float* __restrict__ w) {
    typedef cub::BlockRadixSort<unsigned int, 256, 4, int, 5> Sorter;
    __shared__ typename Sorter::TempStorage temp;

    const int b = blockIdx.y;
    const int c = blockIdx.x;
    const int t = threadIdx.x;

    unsigned int keys[4];
    int vals[4];
#pragma unroll
    for (int p = 0; p < 4; p++) {
        int i = c * CHUNK + 4 * t + p;
        unsigned int u = __float_as_uint(w[b * NN + i]);
        unsigned int mono = (u & 0x80000000u) ? ~u : (u | 0x80000000u);
        keys[p] = ~mono;
        vals[p] = i;
    }

    Sorter(temp).Sort(keys, vals);   // stable, blocked arrangement

#pragma unroll
    for (int p = 0; p < 4; p++)
        g_run[b * NN + c * CHUNK + 4 * t + p] =
            ((u64)keys[p] << 32) | (unsigned int)vals[p];
}

// ---------------------------------------------------------------------------
// S2: rank + scatter, shared-memory staged, 1 element/thread (max
// parallelism: 256 CTAs). rank = local pos + sum over the other 3 runs of
// exact count(< key): 3 interleaved fixed-step binary searches + correction
// probe (exact lower_bound incl. the count==1024 case).
// ---------------------------------------------------------------------------
__global__ __launch_bounds__(256) void rank_scatter_kernel() {
    __shared__ u64 runs[NN];    // 32 KB: all 4 runs of this batch
    const int b = blockIdx.y;
    const int i = blockIdx.x * 256 + threadIdx.x;   // 0..4095

    const u64* base = g_run + b * NN;
#pragma unroll
    for (int s = 0; s < NN / 256; s++)
        runs[threadIdx.x + s * 256] = base[threadIdx.x + s * 256];
    __syncthreads();

    const int r = i >> 10;                           // owning run
    const int p = i & (CHUNK - 1);                   // pos within run
    const u64 key = runs[i];

    const u64* A0 = runs + (((r + 1) & 3) << 10);
    const u64* A1 = runs + (((r + 2) & 3) << 10);
    const u64* A2 = runs + (((r + 3) & 3) << 10);

    int c0 = 0, c1 = 0, c2 = 0;
#pragma unroll
    for (int step = CHUNK / 2; step > 0; step >>= 1) {
        if (A0[c0 + step - 1] < key) c0 += step;
        if (A1[c1 + step - 1] < key) c1 += step;
        if (A2[c2 + step - 1] < key) c2 += step;
    }
    // fixed steps sum to 1023; count may be 1024 (all smaller)
    if (A0[c0] < key) c0++;
    if (A1[c1] < key) c1++;
    if (A2[c2] < key) c2++;

    const int rank = p + c0 + c1 + c2;
    g_sorted[b * NN + rank] = (int)(key & 0xFFFFFFFFu);
}

// ---------------------------------------------------------------------------
// Fused gather/sum/mix, asymmetric grid: per batch, blocks [0,PRCH) each sum
// 64 pruned rows into one partial (launched first -- they run longest); the
// last-arriving sum CTA per batch (release-fence + ticket + acquire-fence)
// reduces the 32 L2-resident partials into the mix row. Blocks
// [PRCH, PRCH+SELGROUPS) copy 16 selected rows each, in two 8-row batches
// (8 outstanding loads/thread -- per-thread MLP beats occupancy here; no
// min-blocks cap, regs ~78, measured 6.5+ TB/s in this config).
// Every seq byte read exactly once; streaming loads/stores (data >> L2).
// ---------------------------------------------------------------------------
__global__ __launch_bounds__(256) void gather_sum_kernel(const float4* __restrict__ seq,
                                                         float4* __restrict__ out) {
    const int b = blockIdx.y;
    const int g = blockIdx.x;
    const int tid = threadIdx.x;

    const float4* sb = seq + (size_t)b * NN * D4;

    if (g < PRCH) {
        // pruned-sum CTA: tokens at sorted positions [KK + g*64, KK + (g+1)*64)
        __shared__ int toks[PR_GROUP];
        __shared__ int ticket;
        if (tid < PR_GROUP) toks[tid] = g_sorted[b * NN + KK + g * PR_GROUP + tid];
        __syncthreads();

        float4 acc = make_float4(0.f, 0.f, 0.f, 0.f);
#pragma unroll 8
        for (int t = 0; t < PR_GROUP; t++) {
            float4 v = __ldcs(sb + (size_t)toks[t] * D4 + tid);
            acc.x += v.x; acc.y += v.y; acc.z += v.z; acc.w += v.w;
        }
        float4* part = reinterpret_cast<float4*>(g_partial);
        part[((size_t)b * PRCH + g) * D4 + tid] = acc;

        // release: partial visible before ticket
        __threadfence();
        if (tid == 0) ticket = atomicAdd(&g_count_mix[b], 1);
        __syncthreads();
        if (ticket == PRCH - 1) {
            // acquire: order partial reads after observing the last ticket
            __threadfence();
            const float4* pbase = part + (size_t)b * PRCH * D4 + tid;
            float4 s = make_float4(0.f, 0.f, 0.f, 0.f);
#pragma unroll
            for (int c = 0; c < PRCH; c++) {
                float4 v = __ldcg(pbase + (size_t)c * D4);
                s.x += v.x; s.y += v.y; s.z += v.z; s.w += v.w;
            }
            const float scale = 0.05f / (2048.0f + 1e-10f);
            s.x *= scale; s.y *= scale; s.z *= scale; s.w *= scale;
            out[((size_t)b * (KK + 1) + KK) * D4 + tid] = s;
            if (tid == 0) g_count_mix[b] = 0;   // reset for next graph replay
        }
    } else {
        // copy CTA: sorted positions [j0, j0+16), two 8-row batches
        const int j0 = (g - PRCH) * GROUP;
        __shared__ int toks[GROUP];
        if (tid < GROUP) toks[tid] = g_sorted[b * NN + j0 + tid];
        __syncthreads();

        float4* dst = out + ((size_t)b * (KK + 1) + j0) * D4 + tid;
#pragma unroll
        for (int h = 0; h < 2; h++) {
            float4 v[8];
#pragma unroll
            for (int t = 0; t < 8; t++)
                v[t] = __ldcs(sb + (size_t)toks[h * 8 + t] * D4 + tid);
#pragma unroll
            for (int t = 0; t < 8; t++)
                __stcs(dst + (size_t)(h * 8 + t) * D4, v[t]);
        }
    }
}

// ---------------------------------------------------------------------------
extern "C" void kernel_launch(void* const* d_in, const int* in_sizes, int n_in,
                              void* d_out, int out_size) {
    const float* seq = (const float*)d_in[0];
    const float* attn_weights = (const float*)d_in[1];
    float* out = (float*)d_out;
    (void)in_sizes; (void)n_in; (void)out_size;

    dim3 sgrid(NRUNS, BB);                // (4, 16)
    sort_chunks_kernel<<<sgrid, 256>>>(attn_weights);

    dim3 rgrid(NN / 256, BB);             // (16, 16)
    rank_scatter_kernel<<<rgrid, 256>>>();

    dim3 fgrid(PRCH + SELGROUPS, BB);     // (160, 16)
    gather_sum_kernel<<<fgrid, 256>>>((const float4*)seq, (float4*)out);
}

// round 13
// speedup vs baseline: 1.1099x; 1.0206x over previous
#include <cuda_runtime.h>
#include <stdint.h>
#include <cub/block/block_radix_sort.cuh>

// Shapes (fixed): seq (16,4096,1024) f32, attn_weights (16,4096) f32,
// out (16,2049,1024) f32.
#define BB 16
#define NN 4096
#define DD 1024
#define KK 2048
#define D4 (DD / 4)
#define CHUNK 512                     // elements per chunk-sort CTA
#define NRUNS (NN / CHUNK)            // 8 sorted runs per batch
#define GROUP 16                      // rows per copy CTA
#define SELGROUPS (KK / GROUP)        // 128 copy CTAs per batch
#define PR_GROUP 64                   // rows per pruned-sum CTA
#define PRCH (KK / PR_GROUP)          // 32 pruned partials per batch

typedef unsigned long long u64;

__device__ u64   g_run[BB * NN];               // chunk-sorted composite keys
__device__ int   g_sorted[BB * NN];
__device__ float g_partial[BB * PRCH * DD];    // 2 MB scratch
__device__ int   g_count_mix[BB];              // mix tickets (self-resetting)

// ---------------------------------------------------------------------------
// S1: sort 8 chunks of 512 per batch. Grid (8, BB) = 128 CTAs, 256 threads
// x 2 items: same scan width as the 256x4 config but half the per-thread
// serial rank/exchange work per pass (the latency-bound part).
// Key = ~mono(f32) (ascending u32 == descending weight); CUB stable sort
// preserves ascending index on ties. Packed u64 = (key<<32)|idx gives the
// rank kernel a unique comparison value; composite order == jax.lax.top_k
// order (desc value, asc index on ties).
// ---------------------------------------------------------------------------
__global__ __launch_bounds__(256) void sort_chunks_kernel(const float* __restrict__ w) {
    typedef cub::BlockRadixSort<unsigned int, 256, 2, int, 5> Sorter;
    __shared__ typename Sorter::TempStorage temp;

    const int b = blockIdx.y;
    const int c = blockIdx.x;
    const int t = threadIdx.x;

    unsigned int keys[2];
    int vals[2];
#pragma unroll
    for (int p = 0; p < 2; p++) {
        int i = c * CHUNK + 2 * t + p;
        unsigned int u = __float_as_uint(w[b * NN + i]);
        unsigned int mono = (u & 0x80000000u) ? ~u : (u | 0x80000000u);
        keys[p] = ~mono;
        vals[p] = i;
    }

    Sorter(temp).Sort(keys, vals);   // stable, blocked arrangement

#pragma unroll
    for (int p = 0; p < 2; p++)
        g_run[b * NN + c * CHUNK + 2 * t + p] =
            ((u64)keys[p] << 32) | (unsigned int)vals[p];
}

// ---------------------------------------------------------------------------
// S2: rank + scatter, shared-memory staged, 1 element/thread (256 CTAs).
// rank = local pos + sum over the other 7 runs of exact count(< key):
// 7 interleaved fixed-step binary searches (9 rounds, LDS-latency) plus a
// correction probe (exact lower_bound incl. the count==512 case).
// ---------------------------------------------------------------------------
__global__ __launch_bounds__(256) void rank_scatter_kernel() {
    __shared__ u64 runs[NN];    // 32 KB: all 8 runs of this batch
    const int b = blockIdx.y;
    const int i = blockIdx.x * 256 + threadIdx.x;   // 0..4095

    const u64* base = g_run + b * NN;
#pragma unroll
    for (int s = 0; s < NN / 256; s++)
        runs[threadIdx.x + s * 256] = base[threadIdx.x + s * 256];
    __syncthreads();

    const int r = i >> 9;                            // owning run
    const int p = i & (CHUNK - 1);                   // pos within run
    const u64 key = runs[i];

    const u64* A[7];
    int cnt[7];
#pragma unroll
    for (int q = 0; q < 7; q++) {
        A[q] = runs + (((r + 1 + q) & 7) << 9);
        cnt[q] = 0;
    }

#pragma unroll
    for (int step = CHUNK / 2; step > 0; step >>= 1) {
#pragma unroll
        for (int q = 0; q < 7; q++)
            if (A[q][cnt[q] + step - 1] < key) cnt[q] += step;
    }
    // fixed steps sum to 511; count may be 512 (all smaller)
#pragma unroll
    for (int q = 0; q < 7; q++)
        if (A[q][cnt[q]] < key) cnt[q]++;

    int rank = p;
#pragma unroll
    for (int q = 0; q < 7; q++) rank += cnt[q];
    g_sorted[b * NN + rank] = (int)(key & 0xFFFFFFFFu);
}

// ---------------------------------------------------------------------------
// Fused gather/sum/mix, asymmetric grid: per batch, blocks [0,PRCH) each sum
// 64 pruned rows into one partial (launched first -- they run longest); the
// last-arriving sum CTA per batch (release-fence + ticket + acquire-fence)
// reduces the 32 L2-resident partials into the mix row. Blocks
// [PRCH, PRCH+SELGROUPS) copy 16 selected rows each, in two 8-row batches
// (8 outstanding loads/thread: per-thread MLP beats occupancy here).
// Every seq byte read exactly once; streaming loads/stores (data >> L2).
// ---------------------------------------------------------------------------
__global__ __launch_bounds__(256) void gather_sum_kernel(const float4* __restrict__ seq,
                                                         float4* __restrict__ out) {
    const int b = blockIdx.y;
    const int g = blockIdx.x;
    const int tid = threadIdx.x;

    const float4* sb = seq + (size_t)b * NN * D4;

    if (g < PRCH) {
        // pruned-sum CTA: tokens at sorted positions [KK + g*64, KK + (g+1)*64)
        __shared__ int toks[PR_GROUP];
        __shared__ int ticket;
        if (tid < PR_GROUP) toks[tid] = g_sorted[b * NN + KK + g * PR_GROUP + tid];
        __syncthreads();

        float4 acc = make_float4(0.f, 0.f, 0.f, 0.f);
#pragma unroll 8
        for (int t = 0; t < PR_GROUP; t++) {
            float4 v = __ldcs(sb + (size_t)toks[t] * D4 + tid);
            acc.x += v.x; acc.y += v.y; acc.z += v.z; acc.w += v.w;
        }
        float4* part = reinterpret_cast<float4*>(g_partial);
        part[((size_t)b * PRCH + g) * D4 + tid] = acc;

        // release: partial visible before ticket
        __threadfence();
        if (tid == 0) ticket = atomicAdd(&g_count_mix[b], 1);
        __syncthreads();
        if (ticket == PRCH - 1) {
            // acquire: order partial reads after observing the last ticket
            __threadfence();
            const float4* pbase = part + (size_t)b * PRCH * D4 + tid;
            float4 s = make_float4(0.f, 0.f, 0.f, 0.f);
#pragma unroll
            for (int c = 0; c < PRCH; c++) {
                float4 v = __ldcg(pbase + (size_t)c * D4);
                s.x += v.x; s.y += v.y; s.z += v.z; s.w += v.w;
            }
            const float scale = 0.05f / (2048.0f + 1e-10f);
            s.x *= scale; s.y *= scale; s.z *= scale; s.w *= scale;
            out[((size_t)b * (KK + 1) + KK) * D4 + tid] = s;
            if (tid == 0) g_count_mix[b] = 0;   // reset for next graph replay
        }
    } else {
        // copy CTA: sorted positions [j0, j0+16), two 8-row batches
        const int j0 = (g - PRCH) * GROUP;
        __shared__ int toks[GROUP];
        if (tid < GROUP) toks[tid] = g_sorted[b * NN + j0 + tid];
        __syncthreads();

        float4* dst = out + ((size_t)b * (KK + 1) + j0) * D4 + tid;
#pragma unroll
        for (int h = 0; h < 2; h++) {
            float4 v[8];
#pragma unroll
            for (int t = 0; t < 8; t++)
                v[t] = __ldcs(sb + (size_t)toks[h * 8 + t] * D4 + tid);
#pragma unroll
            for (int t = 0; t < 8; t++)
                __stcs(dst + (size_t)(h * 8 + t) * D4, v[t]);
        }
    }
}

// ---------------------------------------------------------------------------
extern "C" void kernel_launch(void* const* d_in, const int* in_sizes, int n_in,
                              void* d_out, int out_size) {
    const float* seq = (const float*)d_in[0];
    const float* attn_weights = (const float*)d_in[1];
    float* out = (float*)d_out;
    (void)in_sizes; (void)n_in; (void)out_size;

    dim3 sgrid(NRUNS, BB);                // (8, 16)
    sort_chunks_kernel<<<sgrid, 256>>>(attn_weights);

    dim3 rgrid(NN / 256, BB);             // (16, 16)
    rank_scatter_kernel<<<rgrid, 256>>>();

    dim3 fgrid(PRCH + SELGROUPS, BB);     // (160, 16)
    gather_sum_kernel<<<fgrid, 256>>>((const float4*)seq, (float4*)out);
}